// round 10
// baseline (speedup 1.0000x reference)
#include <cuda_runtime.h>
#include <cuda_bf16.h>
#include <cstdint>

#define NMAX 50000
#define EPS  1e-5f
#define PPB  32          // points per block (4 sub-batches of 8)
#define RSTB 144         // bf16 tile row stride in BYTES (64 bf16 data + pad)
#define PSTB 160         // p-tile row stride in BYTES
#define LCHB 2304        // per-warp logits chunk bytes (16 rows x 144)
#define LRST 272         // logits row stride bytes (68 floats)

// ---------------- scratch (static device arrays: allocation-free) ----------
__device__ float g_q[NMAX * 64];
__device__ float g_k[NMAX * 64];
__device__ float g_v[NMAX * 64];

// ---------------- mma / ldmatrix helpers ------------------------------------
__device__ __forceinline__ uint32_t smem_u32(const void* p) {
    uint32_t a;
    asm("{ .reg .u64 t; cvta.to.shared.u64 t, %1; cvt.u32.u64 %0, t; }" : "=r"(a) : "l"(p));
    return a;
}
__device__ __forceinline__ void ldsm4(uint32_t* r, uint32_t addr) {
    asm volatile("ldmatrix.sync.aligned.m8n8.x4.shared.b16 {%0,%1,%2,%3},[%4];"
        : "=r"(r[0]), "=r"(r[1]), "=r"(r[2]), "=r"(r[3]) : "r"(addr));
}
__device__ __forceinline__ void ldsm4t(uint32_t* r, uint32_t addr) {
    asm volatile("ldmatrix.sync.aligned.m8n8.x4.trans.shared.b16 {%0,%1,%2,%3},[%4];"
        : "=r"(r[0]), "=r"(r[1]), "=r"(r[2]), "=r"(r[3]) : "r"(addr));
}
__device__ __forceinline__ void mma_bf16(float* c, const uint32_t* a, const uint32_t* b) {
    asm volatile("mma.sync.aligned.m16n8k16.row.col.f32.bf16.bf16.f32 "
        "{%0,%1,%2,%3},{%4,%5,%6,%7},{%8,%9},{%0,%1,%2,%3};"
        : "+f"(c[0]), "+f"(c[1]), "+f"(c[2]), "+f"(c[3])
        : "r"(a[0]), "r"(a[1]), "r"(a[2]), "r"(a[3]), "r"(b[0]), "r"(b[1]));
}
__device__ __forceinline__ void split2(float x0, float x1, uint32_t& hi, uint32_t& lo) {
    __nv_bfloat162 h = __floats2bfloat162_rn(x0, x1);
    hi = *(uint32_t*)&h;
    __nv_bfloat162 l = __floats2bfloat162_rn(x0 - __bfloat162float(h.x),
                                             x1 - __bfloat162float(h.y));
    lo = *(uint32_t*)&l;
}
__device__ __forceinline__ void split8(const float* o, uint4& h4, uint4& l4) {
    split2(o[0], o[1], h4.x, l4.x);
    split2(o[2], o[3], h4.y, l4.y);
    split2(o[4], o[5], h4.z, l4.z);
    split2(o[6], o[7], h4.w, l4.w);
}

// GEMM core: acc(16x64 per warp) = Ahi*Bhi + Alo*Bhi + Ahi*Blo
__device__ __forceinline__ void gemm_frags(
    float acc[8][4], const uint32_t Ah[4][4], const uint32_t Al[4][4],
    uint32_t wbaseH, uint32_t wbaseL, int lid)
{
    #pragma unroll
    for (int nt = 0; nt < 8; nt++)
        #pragma unroll
        for (int i = 0; i < 4; i++) acc[nt][i] = 0.f;
    const uint32_t colb = (uint32_t)(lid & 15) * RSTB + (uint32_t)(lid >> 4) * 16;
    #pragma unroll
    for (int p = 0; p < 4; p++) {
        const uint32_t cofs = colb + (uint32_t)(p * 32);
        uint32_t bh[4][4], bl[4][4];
        #pragma unroll
        for (int k = 0; k < 4; k++) ldsm4t(bh[k], wbaseH + (uint32_t)(k * 16) * RSTB + cofs);
        #pragma unroll
        for (int k = 0; k < 4; k++) { mma_bf16(acc[2*p], Ah[k], &bh[k][0]); mma_bf16(acc[2*p+1], Ah[k], &bh[k][2]); }
        #pragma unroll
        for (int k = 0; k < 4; k++) ldsm4t(bl[k], wbaseL + (uint32_t)(k * 16) * RSTB + cofs);
        #pragma unroll
        for (int k = 0; k < 4; k++) { mma_bf16(acc[2*p], Al[k], &bh[k][0]); mma_bf16(acc[2*p+1], Al[k], &bh[k][2]); }
        #pragma unroll
        for (int k = 0; k < 4; k++) { mma_bf16(acc[2*p], Ah[k], &bl[k][0]); mma_bf16(acc[2*p+1], Ah[k], &bl[k][2]); }
    }
}

// ======================= kernel 1: q/k/v projections (HMMA) =================
#define QOFF_W    0              // 3 x (hi 9216 + lo 9216) = 55296
#define QOFF_AH   55296
#define QOFF_AL   73728
#define QOFF_BIAS 92160          // 192 floats
#define QSMEM_BYTES 92928

__global__ __launch_bounds__(256, 2) void qkv_kernel(
    const float* __restrict__ feat,
    const float* __restrict__ wq, const float* __restrict__ bq,
    const float* __restrict__ wk, const float* __restrict__ bk,
    const float* __restrict__ wv, const float* __restrict__ bv,
    int n)
{
    extern __shared__ char qsm[];
    float* qbias = (float*)(qsm + QOFF_BIAS);
    const int t   = threadIdx.x;
    const int wid = t >> 5;
    const int lid = t & 31;
    const int row0 = blockIdx.x * 128;
    const uint32_t sbase = smem_u32(qsm);

    const float* Wm[3] = { wq, wk, wv };
    const float* Bm[3] = { bq, bk, bv };

    for (int idx = t; idx < 384; idx += 256) {
        const int m  = idx / 128;
        const int rw = (idx & 127) >> 1;
        const int hf = (idx & 1) * 32;
        const float* w = Wm[m];
        char* dH = qsm + QOFF_W + m * 18432 + rw * RSTB;
        char* dL = dH + 9216;
        #pragma unroll
        for (int c8 = 0; c8 < 32; c8 += 8) {
            int c = hf + c8;
            float o[8];
            float4 f0 = __ldg((const float4*)&w[rw * 64 + c]);
            float4 f1 = __ldg((const float4*)&w[rw * 64 + c + 4]);
            o[0]=f0.x; o[1]=f0.y; o[2]=f0.z; o[3]=f0.w;
            o[4]=f1.x; o[5]=f1.y; o[6]=f1.z; o[7]=f1.w;
            uint4 h4, l4;
            split8(o, h4, l4);
            *(uint4*)(dH + c * 2) = h4;
            *(uint4*)(dL + c * 2) = l4;
        }
    }
    if (t < 192) qbias[t] = __ldg(&Bm[t >> 6][t & 63]);

    {
        const int r  = t >> 1;
        const int hf = (t & 1) * 32;
        const int gr = row0 + r;
        char* pH = qsm + QOFF_AH + r * RSTB;
        char* pL = qsm + QOFF_AL + r * RSTB;
        #pragma unroll
        for (int c8 = 0; c8 < 32; c8 += 8) {
            int c = hf + c8;
            float o[8] = {0,0,0,0,0,0,0,0};
            if (gr < n) {
                float4 f0 = __ldg((const float4*)&feat[gr * 64 + c]);
                float4 f1 = __ldg((const float4*)&feat[gr * 64 + c + 4]);
                o[0]=f0.x; o[1]=f0.y; o[2]=f0.z; o[3]=f0.w;
                o[4]=f1.x; o[5]=f1.y; o[6]=f1.z; o[7]=f1.w;
            }
            uint4 h4, l4;
            split8(o, h4, l4);
            *(uint4*)(pH + c * 2) = h4;
            *(uint4*)(pL + c * 2) = l4;
        }
    }
    __syncthreads();

    const int q  = lid >> 3;
    const int rl = lid & 7;
    uint32_t aoff[4];
    #pragma unroll
    for (int k = 0; k < 4; k++)
        aoff[k] = (uint32_t)(wid * 16 + rl + (q & 1) * 8) * RSTB
                + (uint32_t)(k * 32) + (uint32_t)((q >> 1) * 16);
    uint32_t Ah[4][4], Al[4][4];
    #pragma unroll
    for (int k = 0; k < 4; k++) {
        ldsm4(Ah[k], sbase + QOFF_AH + aoff[k]);
        ldsm4(Al[k], sbase + QOFF_AL + aoff[k]);
    }

    const int dr = lid >> 2;
    const int dc = (lid & 3) * 2;
    float* Om[3] = { g_q, g_k, g_v };
    float acc[8][4];

    #pragma unroll
    for (int m = 0; m < 3; m++) {
        gemm_frags(acc, Ah, Al, sbase + QOFF_W + m * 18432,
                   sbase + QOFF_W + m * 18432 + 9216, lid);
        const int grA = row0 + wid * 16 + dr;
        const int grB = grA + 8;
        #pragma unroll
        for (int nt = 0; nt < 8; nt++) {
            int c = nt * 8 + dc;
            float b0 = qbias[m * 64 + c], b1 = qbias[m * 64 + c + 1];
            if (grA < n) *(float2*)&Om[m][grA * 64 + c] = make_float2(acc[nt][0] + b0, acc[nt][1] + b1);
            if (grB < n) *(float2*)&Om[m][grB * 64 + c] = make_float2(acc[nt][2] + b0, acc[nt][3] + b1);
        }
    }
}

// ======================= kernel 2: bf16 HMMA fused kernel (256 thr) =========
// All per-sub-batch dataflow is warp-local except s_o (one block sync).
#define OFF_W1H  0
#define OFF_W1L  9216
#define OFF_W2H  18432
#define OFF_W2L  27648
#define OFF_AH   36864         // A tile hi (also per-warp logits chunks)
#define OFF_AL   55296         // A tile lo (also per-warp logits chunks)
#define OFF_PT   73728         // p tile bf16: 128 rows x PSTB = 20480
#define OFF_ST   94208         // stats: 128 x 8 floats = 4096
#define OFF_SO   98304         // s_o double buffer: 2 x 512 floats = 4096
#define OFF_SV   102400        // 384 floats (bg1,gg,betag,bg2,bo,mom14)
#define OFF_SVP  103936        // svp4: 64 x float4 {wx,wy,wz,bp}
#define OFF_SVG  104960        // svg2: 64 x float2 {gp,betap}
#define SMEM_BYTES 105472

__global__ __launch_bounds__(256, 2) void fused_kernel(
    const float* __restrict__ points,
    const float* __restrict__ feat,
    const int*   __restrict__ nbr,
    const float* __restrict__ wp,  const float* __restrict__ bp,
    const float* __restrict__ gp,  const float* __restrict__ betap,
    const float* __restrict__ wg1, const float* __restrict__ bg1,
    const float* __restrict__ gg,  const float* __restrict__ betag,
    const float* __restrict__ wg2, const float* __restrict__ bg2,
    const float* __restrict__ wo,  const float* __restrict__ bo,
    float* __restrict__ outp, int n)
{
    extern __shared__ char smb[];
    float* s_st = (float*)(smb + OFF_ST);
    float* s_o  = (float*)(smb + OFF_SO);
    float* sv   = (float*)(smb + OFF_SV);
    float4* svp4 = (float4*)(smb + OFF_SVP);
    float2* svg2 = (float2*)(smb + OFF_SVG);

    const int t   = threadIdx.x;
    const int wid = t >> 5;
    const int lid = t & 31;
    const uint32_t sbase = smem_u32(smb);

    if (t < 64) {
        sv[t]       = bg1[t];   sv[64 + t]  = gg[t];   sv[128 + t] = betag[t];
        sv[192 + t] = bg2[t];   sv[256 + t] = bo[t];
        svp4[t] = make_float4(wp[t], wp[64 + t], wp[128 + t], bp[t]);
        svg2[t] = make_float2(gp[t], betap[t]);
    }

    // ---- weight moments (warp 7, 14 sums) ----
    if (wid == 7) {
        int c = lid * 2;
        float wx0 = __ldg(&wp[c]),       wx1 = __ldg(&wp[c + 1]);
        float wy0 = __ldg(&wp[64 + c]),  wy1 = __ldg(&wp[64 + c + 1]);
        float wz0 = __ldg(&wp[128 + c]), wz1 = __ldg(&wp[128 + c + 1]);
        float b0  = __ldg(&bp[c]),       b1  = __ldg(&bp[c + 1]);
        float m[14];
        m[0] = wx0 + wx1;             m[1] = wy0 + wy1;
        m[2] = wz0 + wz1;             m[3] = b0 + b1;
        m[4] = wx0*wx0 + wx1*wx1;     m[5] = wy0*wy0 + wy1*wy1;
        m[6] = wz0*wz0 + wz1*wz1;     m[7] = wx0*wy0 + wx1*wy1;
        m[8] = wx0*wz0 + wx1*wz1;     m[9] = wy0*wz0 + wy1*wz1;
        m[10] = wx0*b0 + wx1*b1;      m[11] = wy0*b0 + wy1*b1;
        m[12] = wz0*b0 + wz1*b1;      m[13] = b0*b0 + b1*b1;
        #pragma unroll
        for (int mk = 1; mk < 32; mk <<= 1)
            #pragma unroll
            for (int i = 0; i < 14; i++)
                m[i] += __shfl_xor_sync(0xffffffffu, m[i], mk);
        if (lid == 0)
            #pragma unroll
            for (int i = 0; i < 14; i++) sv[320 + i] = m[i];
    }

    // ---- stage GEMM weights: bf16 hi/lo split ----
    {
        const int rw  = t & 63;
        const int sel = t >> 6;
        const int m   = sel >> 1;
        const int hf  = (sel & 1) * 32;
        const float* w = m ? wg2 : wg1;
        char* dH = smb + (m ? OFF_W2H : OFF_W1H) + rw * RSTB;
        char* dL = smb + (m ? OFF_W2L : OFF_W1L) + rw * RSTB;
        #pragma unroll
        for (int c8 = 0; c8 < 32; c8 += 8) {
            int c = hf + c8;
            float o[8];
            float4 f0 = __ldg((const float4*)&w[rw * 64 + c]);
            float4 f1 = __ldg((const float4*)&w[rw * 64 + c + 4]);
            o[0]=f0.x; o[1]=f0.y; o[2]=f0.z; o[3]=f0.w;
            o[4]=f1.x; o[5]=f1.y; o[6]=f1.z; o[7]=f1.w;
            uint4 h4, l4;
            split8(o, h4, l4);
            *(uint4*)(dH + c * 2) = h4;
            *(uint4*)(dL + c * 2) = l4;
        }
    }
    __syncthreads();

    // fragment geometry: warp wid owns rows [wid*16, wid*16+16) = ONE point
    const int q  = lid >> 3;
    const int rl = lid & 7;
    uint32_t aoff[4];
    #pragma unroll
    for (int k = 0; k < 4; k++)
        aoff[k] = (uint32_t)(wid * 16 + rl + (q & 1) * 8) * RSTB
                + (uint32_t)(k * 32) + (uint32_t)((q >> 1) * 16);
    const int dr  = lid >> 2;
    const int dc  = (lid & 3) * 2;
    const int rtl = (lid >> 3) & 3;
    const int cg  = lid & 7;
    const int c0  = cg * 8;
    const int c2  = lid * 2;

    float acc[8][4];

    int nb_pref = 0;
    {
        int np0  = blockIdx.x * PPB + wid;
        int npc0 = (np0 < n) ? np0 : 0;
        if (lid < 16) nb_pref = __ldg(&nbr[npc0 * 16 + lid]);
    }

    for (int b = 0; b < 4; b++) {
        const int pbase = blockIdx.x * PPB + b * 8;
        const int pt  = pbase + wid;
        const int ptc = (pt < n) ? pt : 0;

        // ---- q (once per warp per sub-batch) ----
        float2 q2 = *(const float2*)&g_q[(size_t)ptc * 64 + c2];

        // ---- per-row stats: closed-form LN via weight moments (lanes<16) ---
        if (lid < 16) {
            int nb = nb_pref;
            if (b < 3) {
                int np1  = pbase + 8 + wid;
                int npc1 = (np1 < n) ? np1 : 0;
                nb_pref  = __ldg(&nbr[npc1 * 16 + lid]);
            }
            float bx = __ldg(&points[ptc * 3 + 0]);
            float by = __ldg(&points[ptc * 3 + 1]);
            float bz = __ldg(&points[ptc * 3 + 2]);
            float rx = __ldg(&points[nb * 3 + 0]) - bx;
            float ry = __ldg(&points[nb * 3 + 1]) - by;
            float rz = __ldg(&points[nb * 3 + 2]) - bz;
            const float* mom = sv + 320;
            float mu = (rx * mom[0] + ry * mom[1] + rz * mom[2] + mom[3]) * 0.015625f;
            float E2 = (rx*rx*mom[4] + ry*ry*mom[5] + rz*rz*mom[6]
                       + 2.f*(rx*ry*mom[7] + rx*rz*mom[8] + ry*rz*mom[9]
                              + rx*mom[10] + ry*mom[11] + rz*mom[12])
                       + mom[13]) * 0.015625f;
            float rs = rsqrtf(E2 - mu * mu + EPS);
            int row = wid * 16 + lid;
            float* st = s_st + row * 8;
            *(float4*)st = make_float4(rx, ry, rz, mu);
            st[4] = rs;
            st[5] = __int_as_float(nb);
        }
        __syncwarp();

        // ---- gather loop: lane owns 2 channels; 16 coalesced rows ----------
        {
            float4 P0 = svp4[c2], P1 = svp4[c2 + 1];
            float2 G0 = svg2[c2], G1 = svg2[c2 + 1];
            char* pHb = smb + OFF_AH + (wid * 16) * RSTB + lid * 4;
            char* pLb = smb + OFF_AL + (wid * 16) * RSTB + lid * 4;
            char* pPb = smb + OFF_PT + (wid * 16) * PSTB + lid * 4;
            #pragma unroll 4
            for (int rr = 0; rr < 16; rr++) {
                const float* st = s_st + (wid * 16 + rr) * 8;
                float4 sA = *(const float4*)st;
                float2 sB = *(const float2*)(st + 4);
                int nb = __float_as_int(sB.y);
                float2 gk2 = *(const float2*)&g_k[(size_t)nb * 64 + c2];
                float pre0 = fmaf(sA.x, P0.x, fmaf(sA.y, P0.y, fmaf(sA.z, P0.z, P0.w)));
                float pre1 = fmaf(sA.x, P1.x, fmaf(sA.y, P1.y, fmaf(sA.z, P1.z, P1.w)));
                float p0 = fmaxf(fmaf((pre0 - sA.w) * sB.x, G0.x, G0.y), 0.f);
                float p1 = fmaxf(fmaf((pre1 - sA.w) * sB.x, G1.x, G1.y), 0.f);
                __nv_bfloat162 pb2 = __floats2bfloat162_rn(p0, p1);
                *(uint32_t*)(pPb + rr * PSTB) = *(uint32_t*)&pb2;
                uint32_t hw, lw_;
                split2(q2.x - gk2.x + p0, q2.y - gk2.y + p1, hw, lw_);
                *(uint32_t*)(pHb + rr * RSTB) = hw;
                *(uint32_t*)(pLb + rr * RSTB) = lw_;
            }
        }
        __syncwarp();

        // ---- GEMM1 (A-frags from own rows; no block sync needed) -----------
        uint32_t Ah[4][4], Al[4][4];
        #pragma unroll
        for (int k = 0; k < 4; k++) {
            ldsm4(Ah[k], sbase + OFF_AH + aoff[k]);
            ldsm4(Al[k], sbase + OFF_AL + aoff[k]);
        }
        gemm_frags(acc, Ah, Al, sbase + OFF_W1H, sbase + OFF_W1L, lid);

        // ---- bias + in-fragment LN + relu -> A2 fragments ------------------
        uint32_t A2h[4][4], A2l[4][4];
        {
            float va[16], vb[16];
            float s1a = 0.f, s2a = 0.f, s1b = 0.f, s2b = 0.f;
            #pragma unroll
            for (int nt = 0; nt < 8; nt++) {
                int c = nt * 8 + dc;
                float x0 = acc[nt][0] + sv[c];
                float x1 = acc[nt][1] + sv[c + 1];
                float y0 = acc[nt][2] + sv[c];
                float y1 = acc[nt][3] + sv[c + 1];
                va[nt * 2] = x0; va[nt * 2 + 1] = x1;
                vb[nt * 2] = y0; vb[nt * 2 + 1] = y1;
                s1a += x0 + x1; s2a += fmaf(x0, x0, x1 * x1);
                s1b += y0 + y1; s2b += fmaf(y0, y0, y1 * y1);
            }
            #pragma unroll
            for (int mk = 1; mk < 4; mk <<= 1) {
                s1a += __shfl_xor_sync(0xffffffffu, s1a, mk);
                s2a += __shfl_xor_sync(0xffffffffu, s2a, mk);
                s1b += __shfl_xor_sync(0xffffffffu, s1b, mk);
                s2b += __shfl_xor_sync(0xffffffffu, s2b, mk);
            }
            float mua = s1a * 0.015625f;
            float rsa = rsqrtf(s2a * 0.015625f - mua * mua + EPS);
            float mub = s1b * 0.015625f;
            float rsb = rsqrtf(s2b * 0.015625f - mub * mub + EPS);
            #pragma unroll
            for (int nt = 0; nt < 8; nt++) {
                int c = nt * 8 + dc;
                float g0 = sv[64 + c], g1 = sv[64 + c + 1];
                float e0 = sv[128 + c], e1 = sv[128 + c + 1];
                float h0 = fmaxf(fmaf((va[nt*2]   - mua) * rsa, g0, e0), 0.f);
                float h1 = fmaxf(fmaf((va[nt*2+1] - mua) * rsa, g1, e1), 0.f);
                float h2 = fmaxf(fmaf((vb[nt*2]   - mub) * rsb, g0, e0), 0.f);
                float h3 = fmaxf(fmaf((vb[nt*2+1] - mub) * rsb, g1, e1), 0.f);
                int kt = nt >> 1, hh = (nt & 1) * 2;
                split2(h0, h1, A2h[kt][hh],     A2l[kt][hh]);
                split2(h2, h3, A2h[kt][hh + 1], A2l[kt][hh + 1]);
            }
        }

        // ---- GEMM2 from register A-fragments -------------------------------
        gemm_frags(acc, A2h, A2l, sbase + OFF_W2H, sbase + OFF_W2L, lid);

        // ---- logits (+bg2) -> per-warp chunks in dead A region -------------
        {
            float* wrA = (float*)(smb + OFF_AH + wid * LCHB + dr * LRST);
            float* wrB = (float*)(smb + OFF_AL + wid * LCHB + dr * LRST);
            #pragma unroll
            for (int nt = 0; nt < 8; nt++) {
                int c = nt * 8 + dc;
                *(float2*)&wrA[c] = make_float2(acc[nt][0] + sv[192 + c], acc[nt][1] + sv[192 + c + 1]);
                *(float2*)&wrB[c] = make_float2(acc[nt][2] + sv[192 + c], acc[nt][3] + sv[192 + c + 1]);
            }
        }
        __syncwarp();

        // ---- softmax over neighbors + weighted sum (warp = point) ----------
        {
            float lw[4][8], pv[4][8];
            float4 gva[4], gvb[4];
            #pragma unroll
            for (int ii = 0; ii < 4; ii++) {
                int local = ii * 4 + rtl;
                int row = wid * 16 + local;
                const float* wr = (const float*)(smb + (local < 8 ? OFF_AH : OFF_AL)
                                                 + wid * LCHB + (local & 7) * LRST);
                #pragma unroll
                for (int u = 0; u < 4; u++) {
                    float2 l2 = *(const float2*)&wr[c0 + 2 * u];
                    lw[ii][2 * u] = l2.x; lw[ii][2 * u + 1] = l2.y;
                }
                int nb2 = __float_as_int(s_st[row * 8 + 5]);
                gva[ii] = *(const float4*)&g_v[(size_t)nb2 * 64 + c0];
                gvb[ii] = *(const float4*)&g_v[(size_t)nb2 * 64 + c0 + 4];
                uint4 praw = *(const uint4*)(smb + OFF_PT + row * PSTB + cg * 16);
                uint32_t pw[4] = { praw.x, praw.y, praw.z, praw.w };
                #pragma unroll
                for (int u = 0; u < 4; u++) {
                    __nv_bfloat162 bb = *(__nv_bfloat162*)&pw[u];
                    pv[ii][2 * u]     = __bfloat162float(bb.x);
                    pv[ii][2 * u + 1] = __bfloat162float(bb.y);
                }
            }
            float mx[8], se[8], wa[8];
            #pragma unroll
            for (int j = 0; j < 8; j++) {
                float m_ = fmaxf(fmaxf(lw[0][j], lw[1][j]), fmaxf(lw[2][j], lw[3][j]));
                m_ = fmaxf(m_, __shfl_xor_sync(0xffffffffu, m_, 8));
                m_ = fmaxf(m_, __shfl_xor_sync(0xffffffffu, m_, 16));
                mx[j] = m_; se[j] = 0.f; wa[j] = 0.f;
            }
            #pragma unroll
            for (int ii = 0; ii < 4; ii++) {
                #pragma unroll
                for (int j = 0; j < 8; j++) {
                    float gvv = (j < 4) ? (&gva[ii].x)[j] : (&gvb[ii].x)[j - 4];
                    float e = __expf(lw[ii][j] - mx[j]);
                    se[j] += e;
                    wa[j] = fmaf(e, gvv + pv[ii][j], wa[j]);
                }
            }
            #pragma unroll
            for (int j = 0; j < 8; j++) {
                se[j] += __shfl_xor_sync(0xffffffffu, se[j], 8);
                se[j] += __shfl_xor_sync(0xffffffffu, se[j], 16);
                wa[j] += __shfl_xor_sync(0xffffffffu, wa[j], 8);
                wa[j] += __shfl_xor_sync(0xffffffffu, wa[j], 16);
            }
            if (rtl == 0) {
                #pragma unroll
                for (int j = 0; j < 8; j++)
                    s_o[(b & 1) * 512 + wid * 64 + c0 + j] = wa[j] / se[j];
            }
        }
        __syncthreads();

        // ---- epilogue: out = s_o @ wo + bo + residual ----------------------
        {
            const float* soB = s_o + (b & 1) * 512;
            const int c  = t & 63;
            const int pg = t >> 6;
            float accv[2];
            accv[0] = sv[256 + c]; accv[1] = sv[256 + c];
            #pragma unroll 16
            for (int k = 0; k < 64; k++) {
                float w_ = __ldg(&wo[k * 64 + c]);
                accv[0] = fmaf(soB[(pg * 2 + 0) * 64 + k], w_, accv[0]);
                accv[1] = fmaf(soB[(pg * 2 + 1) * 64 + k], w_, accv[1]);
            }
            #pragma unroll
            for (int pp = 0; pp < 2; pp++) {
                int np = pbase + pg * 2 + pp;
                if (np < n) outp[np * 64 + c] = accv[pp] + __ldg(&feat[np * 64 + c]);
            }
        }
    }
}

// ======================= launch =============================================
extern "C" void kernel_launch(void* const* d_in, const int* in_sizes, int n_in,
                              void* d_out, int out_size)
{
    const float* points = (const float*)d_in[0];
    const float* feat   = (const float*)d_in[1];
    const int*   nbr    = (const int*)  d_in[2];
    const float* wq = (const float*)d_in[3];
    const float* bq = (const float*)d_in[4];
    const float* wk = (const float*)d_in[5];
    const float* bk = (const float*)d_in[6];
    const float* wv = (const float*)d_in[7];
    const float* bv = (const float*)d_in[8];
    const float* wp = (const float*)d_in[9];
    const float* bp = (const float*)d_in[10];
    const float* gp = (const float*)d_in[11];
    const float* betap = (const float*)d_in[12];
    const float* wg1 = (const float*)d_in[13];
    const float* bg1 = (const float*)d_in[14];
    const float* gg  = (const float*)d_in[15];
    const float* betag = (const float*)d_in[16];
    const float* wg2 = (const float*)d_in[17];
    const float* bg2 = (const float*)d_in[18];
    const float* wo  = (const float*)d_in[19];
    const float* bo  = (const float*)d_in[20];
    float* outp = (float*)d_out;

    int n = in_sizes[1] / 64;
    if (n > NMAX) n = NMAX;

    cudaFuncSetAttribute(qkv_kernel, cudaFuncAttributeMaxDynamicSharedMemorySize, QSMEM_BYTES);
    qkv_kernel<<<(n + 127) / 128, 256, QSMEM_BYTES>>>(feat, wq, bq, wk, bk, wv, bv, n);

    cudaFuncSetAttribute(fused_kernel, cudaFuncAttributeMaxDynamicSharedMemorySize, SMEM_BYTES);
    fused_kernel<<<(n + PPB - 1) / PPB, 256, SMEM_BYTES>>>(
        points, feat, nbr,
        wp, bp, gp, betap,
        wg1, bg1, gg, betag,
        wg2, bg2, wo, bo,
        outp, n);
}

// round 11
// speedup vs baseline: 1.4085x; 1.4085x over previous
#include <cuda_runtime.h>
#include <cuda_bf16.h>
#include <cstdint>

#define NMAX 50000
#define EPS  1e-5f
#define PPB  32          // points per block (4 sub-batches of 8)
#define RSTB 144         // bf16 tile row stride in BYTES (64 bf16 data + pad)
#define LCHB 2304        // per-warp logits chunk bytes (== 16 A rows)
#define LRST 272         // logits row stride bytes (68 floats)

// ---------------- scratch (static device arrays: allocation-free) ----------
__device__ float g_q[NMAX * 64];
__device__ float g_k[NMAX * 64];
__device__ float g_v[NMAX * 64];

// ---------------- mma / ldmatrix helpers ------------------------------------
__device__ __forceinline__ uint32_t smem_u32(const void* p) {
    uint32_t a;
    asm("{ .reg .u64 t; cvta.to.shared.u64 t, %1; cvt.u32.u64 %0, t; }" : "=r"(a) : "l"(p));
    return a;
}
__device__ __forceinline__ void ldsm4(uint32_t* r, uint32_t addr) {
    asm volatile("ldmatrix.sync.aligned.m8n8.x4.shared.b16 {%0,%1,%2,%3},[%4];"
        : "=r"(r[0]), "=r"(r[1]), "=r"(r[2]), "=r"(r[3]) : "r"(addr));
}
__device__ __forceinline__ void ldsm4t(uint32_t* r, uint32_t addr) {
    asm volatile("ldmatrix.sync.aligned.m8n8.x4.trans.shared.b16 {%0,%1,%2,%3},[%4];"
        : "=r"(r[0]), "=r"(r[1]), "=r"(r[2]), "=r"(r[3]) : "r"(addr));
}
__device__ __forceinline__ void mma_bf16(float* c, const uint32_t* a, const uint32_t* b) {
    asm volatile("mma.sync.aligned.m16n8k16.row.col.f32.bf16.bf16.f32 "
        "{%0,%1,%2,%3},{%4,%5,%6,%7},{%8,%9},{%0,%1,%2,%3};"
        : "+f"(c[0]), "+f"(c[1]), "+f"(c[2]), "+f"(c[3])
        : "r"(a[0]), "r"(a[1]), "r"(a[2]), "r"(a[3]), "r"(b[0]), "r"(b[1]));
}
__device__ __forceinline__ void split2(float x0, float x1, uint32_t& hi, uint32_t& lo) {
    __nv_bfloat162 h = __floats2bfloat162_rn(x0, x1);
    hi = *(uint32_t*)&h;
    __nv_bfloat162 l = __floats2bfloat162_rn(x0 - __bfloat162float(h.x),
                                             x1 - __bfloat162float(h.y));
    lo = *(uint32_t*)&l;
}
__device__ __forceinline__ void split8(const float* o, uint4& h4, uint4& l4) {
    split2(o[0], o[1], h4.x, l4.x);
    split2(o[2], o[3], h4.y, l4.y);
    split2(o[4], o[5], h4.z, l4.z);
    split2(o[6], o[7], h4.w, l4.w);
}

// GEMM core: acc(16x64 per warp) = Ahi*Bhi + Alo*Bhi + Ahi*Blo
__device__ __forceinline__ void gemm_frags(
    float acc[8][4], const uint32_t Ah[4][4], const uint32_t Al[4][4],
    uint32_t wbaseH, uint32_t wbaseL, int lid)
{
    #pragma unroll
    for (int nt = 0; nt < 8; nt++)
        #pragma unroll
        for (int i = 0; i < 4; i++) acc[nt][i] = 0.f;
    const uint32_t colb = (uint32_t)(lid & 15) * RSTB + (uint32_t)(lid >> 4) * 16;
    #pragma unroll
    for (int p = 0; p < 4; p++) {
        const uint32_t cofs = colb + (uint32_t)(p * 32);
        uint32_t bh[4][4], bl[4][4];
        #pragma unroll
        for (int k = 0; k < 4; k++) ldsm4t(bh[k], wbaseH + (uint32_t)(k * 16) * RSTB + cofs);
        #pragma unroll
        for (int k = 0; k < 4; k++) { mma_bf16(acc[2*p], Ah[k], &bh[k][0]); mma_bf16(acc[2*p+1], Ah[k], &bh[k][2]); }
        #pragma unroll
        for (int k = 0; k < 4; k++) ldsm4t(bl[k], wbaseL + (uint32_t)(k * 16) * RSTB + cofs);
        #pragma unroll
        for (int k = 0; k < 4; k++) { mma_bf16(acc[2*p], Al[k], &bh[k][0]); mma_bf16(acc[2*p+1], Al[k], &bh[k][2]); }
        #pragma unroll
        for (int k = 0; k < 4; k++) { mma_bf16(acc[2*p], Ah[k], &bl[k][0]); mma_bf16(acc[2*p+1], Ah[k], &bl[k][2]); }
    }
}

// ======================= kernel 1: q/k/v projections (HMMA) =================
#define QOFF_W    0              // 3 x (hi 9216 + lo 9216) = 55296
#define QOFF_AH   55296
#define QOFF_AL   73728
#define QOFF_BIAS 92160          // 192 floats
#define QSMEM_BYTES 92928

__global__ __launch_bounds__(256, 2) void qkv_kernel(
    const float* __restrict__ feat,
    const float* __restrict__ wq, const float* __restrict__ bq,
    const float* __restrict__ wk, const float* __restrict__ bk,
    const float* __restrict__ wv, const float* __restrict__ bv,
    int n)
{
    extern __shared__ char qsm[];
    float* qbias = (float*)(qsm + QOFF_BIAS);
    const int t   = threadIdx.x;
    const int wid = t >> 5;
    const int lid = t & 31;
    const int row0 = blockIdx.x * 128;
    const uint32_t sbase = smem_u32(qsm);

    const float* Wm[3] = { wq, wk, wv };
    const float* Bm[3] = { bq, bk, bv };

    for (int idx = t; idx < 384; idx += 256) {
        const int m  = idx / 128;
        const int rw = (idx & 127) >> 1;
        const int hf = (idx & 1) * 32;
        const float* w = Wm[m];
        char* dH = qsm + QOFF_W + m * 18432 + rw * RSTB;
        char* dL = dH + 9216;
        #pragma unroll
        for (int c8 = 0; c8 < 32; c8 += 8) {
            int c = hf + c8;
            float o[8];
            float4 f0 = __ldg((const float4*)&w[rw * 64 + c]);
            float4 f1 = __ldg((const float4*)&w[rw * 64 + c + 4]);
            o[0]=f0.x; o[1]=f0.y; o[2]=f0.z; o[3]=f0.w;
            o[4]=f1.x; o[5]=f1.y; o[6]=f1.z; o[7]=f1.w;
            uint4 h4, l4;
            split8(o, h4, l4);
            *(uint4*)(dH + c * 2) = h4;
            *(uint4*)(dL + c * 2) = l4;
        }
    }
    if (t < 192) qbias[t] = __ldg(&Bm[t >> 6][t & 63]);

    {
        const int r  = t >> 1;
        const int hf = (t & 1) * 32;
        const int gr = row0 + r;
        char* pH = qsm + QOFF_AH + r * RSTB;
        char* pL = qsm + QOFF_AL + r * RSTB;
        #pragma unroll
        for (int c8 = 0; c8 < 32; c8 += 8) {
            int c = hf + c8;
            float o[8] = {0,0,0,0,0,0,0,0};
            if (gr < n) {
                float4 f0 = __ldg((const float4*)&feat[gr * 64 + c]);
                float4 f1 = __ldg((const float4*)&feat[gr * 64 + c + 4]);
                o[0]=f0.x; o[1]=f0.y; o[2]=f0.z; o[3]=f0.w;
                o[4]=f1.x; o[5]=f1.y; o[6]=f1.z; o[7]=f1.w;
            }
            uint4 h4, l4;
            split8(o, h4, l4);
            *(uint4*)(pH + c * 2) = h4;
            *(uint4*)(pL + c * 2) = l4;
        }
    }
    __syncthreads();

    const int q  = lid >> 3;
    const int rl = lid & 7;
    uint32_t aoff[4];
    #pragma unroll
    for (int k = 0; k < 4; k++)
        aoff[k] = (uint32_t)(wid * 16 + rl + (q & 1) * 8) * RSTB
                + (uint32_t)(k * 32) + (uint32_t)((q >> 1) * 16);
    uint32_t Ah[4][4], Al[4][4];
    #pragma unroll
    for (int k = 0; k < 4; k++) {
        ldsm4(Ah[k], sbase + QOFF_AH + aoff[k]);
        ldsm4(Al[k], sbase + QOFF_AL + aoff[k]);
    }

    const int dr = lid >> 2;
    const int dc = (lid & 3) * 2;
    float* Om[3] = { g_q, g_k, g_v };
    float acc[8][4];

    #pragma unroll
    for (int m = 0; m < 3; m++) {
        gemm_frags(acc, Ah, Al, sbase + QOFF_W + m * 18432,
                   sbase + QOFF_W + m * 18432 + 9216, lid);
        const int grA = row0 + wid * 16 + dr;
        const int grB = grA + 8;
        #pragma unroll
        for (int nt = 0; nt < 8; nt++) {
            int c = nt * 8 + dc;
            float b0 = qbias[m * 64 + c], b1 = qbias[m * 64 + c + 1];
            if (grA < n) *(float2*)&Om[m][grA * 64 + c] = make_float2(acc[nt][0] + b0, acc[nt][1] + b1);
            if (grB < n) *(float2*)&Om[m][grB * 64 + c] = make_float2(acc[nt][2] + b0, acc[nt][3] + b1);
        }
    }
}

// ======================= kernel 2: bf16 HMMA fused kernel (256 thr) =========
// EVERY per-sub-batch structure is warp-private: phase A rows, A-fragments,
// logits chunks, stats, epilogue. ZERO block barriers in the main loop.
#define OFF_W1H  0
#define OFF_W1L  9216
#define OFF_W2H  18432
#define OFF_W2L  27648
#define OFF_AH   36864         // A tile hi; per-warp logits rows 0-7 overlay
#define OFF_AL   55296         // A tile lo; per-warp logits rows 8-15 overlay
#define OFF_STAT 73728         // rx,ry,rz,mu,rs (5*512B) + nb (512B)
#define OFF_SV   76800         // 768 floats
#define OFF_WO   79872         // wo staged fp32: 16384 bytes
#define SMEM_BYTES 96256

__global__ __launch_bounds__(256, 2) void fused_kernel(
    const float* __restrict__ points,
    const float* __restrict__ feat,
    const int*   __restrict__ nbr,
    const float* __restrict__ wp,  const float* __restrict__ bp,
    const float* __restrict__ gp,  const float* __restrict__ betap,
    const float* __restrict__ wg1, const float* __restrict__ bg1,
    const float* __restrict__ gg,  const float* __restrict__ betag,
    const float* __restrict__ wg2, const float* __restrict__ bg2,
    const float* __restrict__ wo,  const float* __restrict__ bo,
    float* __restrict__ outp, int n)
{
    extern __shared__ char smb[];
    float* s_rx = (float*)(smb + OFF_STAT);
    float* s_ry = s_rx + 128;
    float* s_rz = s_ry + 128;
    float* s_mu = s_rz + 128;
    float* s_rs = s_mu + 128;
    int*   s_nb = (int*)(s_rs + 128);
    float* sv   = (float*)(smb + OFF_SV);
    float* wos  = (float*)(smb + OFF_WO);
    // sv: [0]=bg1 [64]=gg [128]=betag [192]=bg2 [256]=bp [320]=gp [384]=betap
    //     [448]=bo [512..704)=wp rows

    const int t   = threadIdx.x;
    const int wid = t >> 5;
    const int lid = t & 31;
    const uint32_t sbase = smem_u32(smb);

    if (t < 64) {
        sv[t]       = bg1[t];   sv[64 + t]  = gg[t];      sv[128 + t] = betag[t];
        sv[192 + t] = bg2[t];   sv[256 + t] = bp[t];      sv[320 + t] = gp[t];
        sv[384 + t] = betap[t]; sv[448 + t] = bo[t];
        sv[512 + t] = wp[t];    sv[576 + t] = wp[64 + t]; sv[640 + t] = wp[128 + t];
    }
    for (int i = t; i < 1024; i += 256)
        ((float4*)wos)[i] = __ldg(&((const float4*)wo)[i]);

    // ---- stage weights: bf16 hi/lo split, row-major [k][n], stride RSTB ----
    {
        const int rw  = t & 63;
        const int sel = t >> 6;
        const int m   = sel >> 1;
        const int hf  = (sel & 1) * 32;
        const float* w = m ? wg2 : wg1;
        char* dH = smb + (m ? OFF_W2H : OFF_W1H) + rw * RSTB;
        char* dL = smb + (m ? OFF_W2L : OFF_W1L) + rw * RSTB;
        #pragma unroll
        for (int c8 = 0; c8 < 32; c8 += 8) {
            int c = hf + c8;
            float o[8];
            float4 f0 = __ldg((const float4*)&w[rw * 64 + c]);
            float4 f1 = __ldg((const float4*)&w[rw * 64 + c + 4]);
            o[0]=f0.x; o[1]=f0.y; o[2]=f0.z; o[3]=f0.w;
            o[4]=f1.x; o[5]=f1.y; o[6]=f1.z; o[7]=f1.w;
            uint4 h4, l4;
            split8(o, h4, l4);
            *(uint4*)(dH + c * 2) = h4;
            *(uint4*)(dL + c * 2) = l4;
        }
    }
    __syncthreads();   // weights/sv/wos ready; ONLY block barrier in kernel

    // fragment geometry: warp wid owns rows [wid*16, wid*16+16) = ONE point
    const int q  = lid >> 3;
    const int rl = lid & 7;
    uint32_t aoff[4];
    #pragma unroll
    for (int k = 0; k < 4; k++)
        aoff[k] = (uint32_t)(wid * 16 + rl + (q & 1) * 8) * RSTB
                + (uint32_t)(k * 32) + (uint32_t)((q >> 1) * 16);
    const int dr  = lid >> 2;
    const int dc  = (lid & 3) * 2;
    const int rtl = (lid >> 3) & 3;
    const int cg  = lid & 7;
    const int c0  = cg * 8;

    // phase-A row mapping (2 threads per row)
    const int rA  = t >> 1;
    const int haA = t & 1;
    const int jnA = rA & 15;
    const int rqA = rA >> 4;

    float acc[8][4];

    int nb_pref;
    {
        int np0  = blockIdx.x * PPB + rqA;
        int npc0 = (np0 < n) ? np0 : 0;
        nb_pref  = __ldg(&nbr[npc0 * 16 + jnA]);
    }

    for (int b = 0; b < 4; b++) {
        const int pbase = blockIdx.x * PPB + b * 8;

        // ---------------- phase A: 2 threads per row (32 ch each) -----------
        {
            const int r   = rA;
            const int ha  = haA;
            const int cb  = ha * 32;
            const int np  = pbase + rqA;
            const int npc = (np < n) ? np : 0;
            const int nb  = nb_pref;

            float rx = __ldg(&points[nb * 3 + 0]) - __ldg(&points[npc * 3 + 0]);
            float ry = __ldg(&points[nb * 3 + 1]) - __ldg(&points[npc * 3 + 1]);
            float rz = __ldg(&points[nb * 3 + 2]) - __ldg(&points[npc * 3 + 2]);

            if (b < 3) {
                int np1  = pbase + 8 + rqA;
                int npc1 = (np1 < n) ? np1 : 0;
                nb_pref  = __ldg(&nbr[npc1 * 16 + jnA]);
            }

            float pre[32];
            float s1 = 0.f, s2 = 0.f;
            #pragma unroll
            for (int cc = 0; cc < 32; cc++) {
                int c = cb + cc;
                float pr = fmaf(rx, sv[512 + c], fmaf(ry, sv[576 + c], fmaf(rz, sv[640 + c], sv[256 + c])));
                pre[cc] = pr;
                s1 += pr; s2 += pr * pr;
            }
            s1 += __shfl_xor_sync(0xffffffffu, s1, 1);
            s2 += __shfl_xor_sync(0xffffffffu, s2, 1);
            float mu = s1 * 0.015625f;
            float rs = rsqrtf(s2 * 0.015625f - mu * mu + EPS);
            if (ha == 0) {
                s_rx[r] = rx; s_ry[r] = ry; s_rz[r] = rz;
                s_mu[r] = mu; s_rs[r] = rs; s_nb[r] = nb;
            }

            const float* gkp = &g_k[(size_t)nb * 64];
            const float* qp  = &g_q[(size_t)npc * 64];
            char* pH = smb + OFF_AH + r * RSTB;
            char* pL = smb + OFF_AL + r * RSTB;
            #pragma unroll
            for (int g8 = 0; g8 < 32; g8 += 8) {
                int c8 = cb + g8;
                float4 qa = *(const float4*)&qp[c8];
                float4 qb = *(const float4*)&qp[c8 + 4];
                float4 ka = *(const float4*)&gkp[c8];
                float4 kb = *(const float4*)&gkp[c8 + 4];
                float o[8];
                #pragma unroll
                for (int u = 0; u < 8; u++) {
                    int c = c8 + u;
                    float p = fmaxf(fmaf((pre[g8 + u] - mu) * rs, sv[320 + c], sv[384 + c]), 0.f);
                    float qv = (u < 4) ? (&qa.x)[u] : (&qb.x)[u - 4];
                    float kv = (u < 4) ? (&ka.x)[u] : (&kb.x)[u - 4];
                    o[u] = qv - kv + p;
                }
                uint4 h4, l4;
                split8(o, h4, l4);
                *(uint4*)(pH + c8 * 2) = h4;
                *(uint4*)(pL + c8 * 2) = l4;
            }
        }
        __syncwarp();

        // ---------------- GEMM1 (A-frags from own rows) ---------------------
        uint32_t Ah[4][4], Al[4][4];
        #pragma unroll
        for (int k = 0; k < 4; k++) {
            ldsm4(Ah[k], sbase + OFF_AH + aoff[k]);
            ldsm4(Al[k], sbase + OFF_AL + aoff[k]);
        }
        gemm_frags(acc, Ah, Al, sbase + OFF_W1H, sbase + OFF_W1L, lid);

        // ---------------- bias + in-fragment LN + relu -> A2 fragments ------
        uint32_t A2h[4][4], A2l[4][4];
        {
            float va[16], vb[16];
            float s1a = 0.f, s2a = 0.f, s1b = 0.f, s2b = 0.f;
            #pragma unroll
            for (int nt = 0; nt < 8; nt++) {
                int c = nt * 8 + dc;
                float x0 = acc[nt][0] + sv[c];
                float x1 = acc[nt][1] + sv[c + 1];
                float y0 = acc[nt][2] + sv[c];
                float y1 = acc[nt][3] + sv[c + 1];
                va[nt * 2] = x0; va[nt * 2 + 1] = x1;
                vb[nt * 2] = y0; vb[nt * 2 + 1] = y1;
                s1a += x0 + x1; s2a += fmaf(x0, x0, x1 * x1);
                s1b += y0 + y1; s2b += fmaf(y0, y0, y1 * y1);
            }
            #pragma unroll
            for (int mk = 1; mk < 4; mk <<= 1) {
                s1a += __shfl_xor_sync(0xffffffffu, s1a, mk);
                s2a += __shfl_xor_sync(0xffffffffu, s2a, mk);
                s1b += __shfl_xor_sync(0xffffffffu, s1b, mk);
                s2b += __shfl_xor_sync(0xffffffffu, s2b, mk);
            }
            float mua = s1a * 0.015625f;
            float rsa = rsqrtf(s2a * 0.015625f - mua * mua + EPS);
            float mub = s1b * 0.015625f;
            float rsb = rsqrtf(s2b * 0.015625f - mub * mub + EPS);
            #pragma unroll
            for (int nt = 0; nt < 8; nt++) {
                int c = nt * 8 + dc;
                float g0 = sv[64 + c], g1 = sv[64 + c + 1];
                float e0 = sv[128 + c], e1 = sv[128 + c + 1];
                float h0 = fmaxf(fmaf((va[nt*2]   - mua) * rsa, g0, e0), 0.f);
                float h1 = fmaxf(fmaf((va[nt*2+1] - mua) * rsa, g1, e1), 0.f);
                float h2 = fmaxf(fmaf((vb[nt*2]   - mub) * rsb, g0, e0), 0.f);
                float h3 = fmaxf(fmaf((vb[nt*2+1] - mub) * rsb, g1, e1), 0.f);
                int kt = nt >> 1, hh = (nt & 1) * 2;
                split2(h0, h1, A2h[kt][hh],     A2l[kt][hh]);
                split2(h2, h3, A2h[kt][hh + 1], A2l[kt][hh + 1]);
            }
        }

        // ---------------- GEMM2 from register A-fragments -------------------
        gemm_frags(acc, A2h, A2l, sbase + OFF_W2H, sbase + OFF_W2L, lid);

        // ---------------- logits (+bg2) -> own per-warp chunks --------------
        // warp's chunk == its own (now dead) A rows: OFF_AH/AL + wid*LCHB
        {
            float* wrA = (float*)(smb + OFF_AH + wid * LCHB + dr * LRST);
            float* wrB = (float*)(smb + OFF_AL + wid * LCHB + dr * LRST);
            #pragma unroll
            for (int nt = 0; nt < 8; nt++) {
                int c = nt * 8 + dc;
                *(float2*)&wrA[c] = make_float2(acc[nt][0] + sv[192 + c], acc[nt][1] + sv[192 + c + 1]);
                *(float2*)&wrB[c] = make_float2(acc[nt][2] + sv[192 + c], acc[nt][3] + sv[192 + c + 1]);
            }
        }
        __syncwarp();

        // -------- softmax over neighbors + weighted sum (warp = point) ------
        float so[8];
        {
            float lw[4][8];
            float4 gva[4], gvb[4];
            int rws[4];
            #pragma unroll
            for (int ii = 0; ii < 4; ii++) {
                int local = ii * 4 + rtl;
                int row = wid * 16 + local;
                rws[ii] = row;
                const float* wr = (const float*)(smb + (local < 8 ? OFF_AH : OFF_AL)
                                                 + wid * LCHB + (local & 7) * LRST);
                #pragma unroll
                for (int u = 0; u < 4; u++) {
                    float2 l2 = *(const float2*)&wr[c0 + 2 * u];
                    lw[ii][2 * u] = l2.x; lw[ii][2 * u + 1] = l2.y;
                }
                int nb2 = s_nb[row];
                gva[ii] = *(const float4*)&g_v[(size_t)nb2 * 64 + c0];
                gvb[ii] = *(const float4*)&g_v[(size_t)nb2 * 64 + c0 + 4];
            }
            float mx[8], se[8], wa[8];
            #pragma unroll
            for (int j = 0; j < 8; j++) {
                float m_ = fmaxf(fmaxf(lw[0][j], lw[1][j]), fmaxf(lw[2][j], lw[3][j]));
                m_ = fmaxf(m_, __shfl_xor_sync(0xffffffffu, m_, 8));
                m_ = fmaxf(m_, __shfl_xor_sync(0xffffffffu, m_, 16));
                mx[j] = m_; se[j] = 0.f; wa[j] = 0.f;
            }
            #pragma unroll
            for (int ii = 0; ii < 4; ii++) {
                int row = rws[ii];
                float rx = s_rx[row], ry = s_ry[row], rz = s_rz[row];
                float mu = s_mu[row], rs = s_rs[row];
                #pragma unroll
                for (int j = 0; j < 8; j++) {
                    int c = c0 + j;
                    float pre = fmaf(rx, sv[512 + c], fmaf(ry, sv[576 + c], fmaf(rz, sv[640 + c], sv[256 + c])));
                    float p = fmaxf(fmaf((pre - mu) * rs, sv[320 + c], sv[384 + c]), 0.f);
                    float gvv = (j < 4) ? (&gva[ii].x)[j] : (&gvb[ii].x)[j - 4];
                    float e = __expf(lw[ii][j] - mx[j]);
                    se[j] += e;
                    wa[j] = fmaf(e, gvv + p, wa[j]);
                }
            }
            #pragma unroll
            for (int j = 0; j < 8; j++) {
                se[j] += __shfl_xor_sync(0xffffffffu, se[j], 8);
                se[j] += __shfl_xor_sync(0xffffffffu, se[j], 16);
                wa[j] += __shfl_xor_sync(0xffffffffu, wa[j], 8);
                wa[j] += __shfl_xor_sync(0xffffffffu, wa[j], 16);
                so[j] = wa[j] / se[j];   // valid on ALL lanes; ch = (lid&7)*8+j
            }
        }

        // ---------------- epilogue (in-warp, shuffle broadcast) -------------
        {
            const int pt = pbase + wid;
            float a0 = sv[448 + lid];
            float a1 = sv[448 + lid + 32];
            #pragma unroll
            for (int g = 0; g < 8; g++) {
                #pragma unroll
                for (int j = 0; j < 8; j++) {
                    float s_ = __shfl_sync(0xffffffffu, so[j], g);
                    int k = g * 8 + j;
                    a0 = fmaf(s_, wos[k * 64 + lid], a0);
                    a1 = fmaf(s_, wos[k * 64 + lid + 32], a1);
                }
            }
            if (pt < n) {
                outp[pt * 64 + lid]      = a0 + __ldg(&feat[pt * 64 + lid]);
                outp[pt * 64 + lid + 32] = a1 + __ldg(&feat[pt * 64 + lid + 32]);
            }
        }
        // no block barrier: all per-sub-batch state is warp-private
    }
}

// ======================= launch =============================================
extern "C" void kernel_launch(void* const* d_in, const int* in_sizes, int n_in,
                              void* d_out, int out_size)
{
    const float* points = (const float*)d_in[0];
    const float* feat   = (const float*)d_in[1];
    const int*   nbr    = (const int*)  d_in[2];
    const float* wq = (const float*)d_in[3];
    const float* bq = (const float*)d_in[4];
    const float* wk = (const float*)d_in[5];
    const float* bk = (const float*)d_in[6];
    const float* wv = (const float*)d_in[7];
    const float* bv = (const float*)d_in[8];
    const float* wp = (const float*)d_in[9];
    const float* bp = (const float*)d_in[10];
    const float* gp = (const float*)d_in[11];
    const float* betap = (const float*)d_in[12];
    const float* wg1 = (const float*)d_in[13];
    const float* bg1 = (const float*)d_in[14];
    const float* gg  = (const float*)d_in[15];
    const float* betag = (const float*)d_in[16];
    const float* wg2 = (const float*)d_in[17];
    const float* bg2 = (const float*)d_in[18];
    const float* wo  = (const float*)d_in[19];
    const float* bo  = (const float*)d_in[20];
    float* outp = (float*)d_out;

    int n = in_sizes[1] / 64;
    if (n > NMAX) n = NMAX;

    cudaFuncSetAttribute(qkv_kernel, cudaFuncAttributeMaxDynamicSharedMemorySize, QSMEM_BYTES);
    qkv_kernel<<<(n + 127) / 128, 256, QSMEM_BYTES>>>(feat, wq, bq, wk, bk, wv, bv, n);

    cudaFuncSetAttribute(fused_kernel, cudaFuncAttributeMaxDynamicSharedMemorySize, SMEM_BYTES);
    fused_kernel<<<(n + PPB - 1) / PPB, 256, SMEM_BYTES>>>(
        points, feat, nbr,
        wp, bp, gp, betap,
        wg1, bg1, gg, betag,
        wg2, bg2, wo, bo,
        outp, n);
}